// round 2
// baseline (speedup 1.0000x reference)
#include <cuda_runtime.h>
#include <cstdint>

// Shapes (fixed for this problem)
#define B_   64
#define N_   2048
#define A_   512
#define RNN_ 1024
#define DW_  1024
#define DS_  1024
#define NCHUNK 16
#define NPER   (N_ / NCHUNK)   // 128

// Scratch (device globals: no allocation allowed)
__device__ float g_hword[B_ * A_];              // 128 KB
__device__ float g_scores[B_ * N_];             // 512 KB (reused as softmax weights)
__device__ float g_partial[B_ * NCHUNK * DW_];  // 4 MB

__device__ __forceinline__ float tanh_fast(float x) {
    float r;
    asm("tanh.approx.f32 %0, %1;" : "=f"(r) : "f"(x));
    return r;
}

__device__ __forceinline__ float warp_sum(float v) {
    #pragma unroll
    for (int o = 16; o; o >>= 1) v += __shfl_xor_sync(0xffffffffu, v, o);
    return v;
}

// ---------------------------------------------------------------------------
// K1: h_word[b,a] = h[b,:] . W[a,:] + bias[a]
// grid = A_ blocks (one per a), 128 threads (4 warps), warps strided over b.
// W row staged in shared (coalesced); h rows read float4-coalesced per lane.
// ---------------------------------------------------------------------------
__global__ void k1_hword(const float* __restrict__ h,
                         const float* __restrict__ W,
                         const float* __restrict__ bias,
                         float* __restrict__ hw) {
    const int a = blockIdx.x;
    __shared__ float sW[RNN_];
    const float4* Wr = (const float4*)(W + (size_t)a * RNN_);
    for (int i = threadIdx.x; i < RNN_ / 4; i += blockDim.x)
        ((float4*)sW)[i] = Wr[i];
    __syncthreads();

    const int warp = threadIdx.x >> 5, lane = threadIdx.x & 31;
    const float bv = bias[a];
    for (int b = warp; b < B_; b += 4) {
        const float4* hb = (const float4*)(h + (size_t)b * RNN_);
        float acc = 0.f;
        #pragma unroll
        for (int i = 0; i < RNN_ / 128; i++) {       // 8 float4 per lane
            float4 v = hb[lane + 32 * i];
            float4 w = ((float4*)sW)[lane + 32 * i];
            acc += v.x * w.x + v.y * w.y + v.z * w.z + v.w * w.w;
        }
        acc = warp_sum(acc);
        if (lane == 0) hw[b * A_ + a] = acc + bv;
    }
}

// ---------------------------------------------------------------------------
// K2: scores[b,n] = sum_a tanh(p[b,n,a] + hw[b,a]) * walpha[a]
// grid = (N_/8, B_), block = 256 (8 warps, one n per warp).
// Streams 268 MB of p; hw row + walpha staged in shared.
// ---------------------------------------------------------------------------
__global__ void k2_scores(const float* __restrict__ p,
                          const float* __restrict__ hw,
                          const float* __restrict__ walpha,
                          float* __restrict__ scores) {
    const int b = blockIdx.y;
    __shared__ float shw[A_];
    __shared__ float swa[A_];
    for (int i = threadIdx.x; i < A_ / 4; i += blockDim.x) {
        ((float4*)shw)[i] = ((const float4*)(hw + (size_t)b * A_))[i];
        ((float4*)swa)[i] = ((const float4*)walpha)[i];
    }
    __syncthreads();

    const int warp = threadIdx.x >> 5, lane = threadIdx.x & 31;
    const int n = blockIdx.x * 8 + warp;
    const float4* pr = (const float4*)(p + ((size_t)b * N_ + n) * A_);

    float acc = 0.f;
    #pragma unroll
    for (int i = 0; i < A_ / 128; i++) {             // 4 float4 per lane
        float4 v  = pr[lane + 32 * i];
        float4 hv = ((float4*)shw)[lane + 32 * i];
        float4 wv = ((float4*)swa)[lane + 32 * i];
        acc += tanh_fast(v.x + hv.x) * wv.x;
        acc += tanh_fast(v.y + hv.y) * wv.y;
        acc += tanh_fast(v.z + hv.z) * wv.z;
        acc += tanh_fast(v.w + hv.w) * wv.w;
    }
    acc = warp_sum(acc);
    if (lane == 0) scores[b * N_ + n] = acc;
}

// ---------------------------------------------------------------------------
// K3: in-place softmax over N per row. grid = B_, block = 256.
// ---------------------------------------------------------------------------
__global__ void k3_softmax(float* __restrict__ scores) {
    const int b = blockIdx.x;
    __shared__ float s[N_];
    __shared__ float red[32];
    float* row = scores + (size_t)b * N_;

    for (int i = threadIdx.x; i < N_ / 4; i += blockDim.x)
        ((float4*)s)[i] = ((float4*)row)[i];
    __syncthreads();

    const int warp = threadIdx.x >> 5, lane = threadIdx.x & 31;

    // max reduce
    float m = -3.4e38f;
    for (int i = threadIdx.x; i < N_; i += blockDim.x) m = fmaxf(m, s[i]);
    #pragma unroll
    for (int o = 16; o; o >>= 1) m = fmaxf(m, __shfl_xor_sync(0xffffffffu, m, o));
    if (lane == 0) red[warp] = m;
    __syncthreads();
    m = red[lane & 7];
    #pragma unroll
    for (int o = 4; o; o >>= 1) m = fmaxf(m, __shfl_xor_sync(0xffffffffu, m, o));
    m = __shfl_sync(0xffffffffu, m, 0);

    // exp + sum
    float sum = 0.f;
    for (int i = threadIdx.x; i < N_; i += blockDim.x) {
        float e = __expf(s[i] - m);
        s[i] = e;
        sum += e;
    }
    sum = warp_sum(sum);
    if (lane == 0) red[warp] = sum;
    __syncthreads();
    sum = red[lane & 7];
    #pragma unroll
    for (int o = 4; o; o >>= 1) sum += __shfl_xor_sync(0xffffffffu, sum, o);
    sum = __shfl_sync(0xffffffffu, sum, 0);
    const float inv = 1.0f / sum;
    __syncthreads();

    for (int i = threadIdx.x; i < N_; i += blockDim.x)
        row[i] = s[i] * inv;
}

// ---------------------------------------------------------------------------
// K4: partial[b,c,d] = sum_{n in chunk c} weight[b,n] * swf[b,n,d]
// grid = (NCHUNK, B_), block = 256; thread t owns float4 d-slot t.
// Streams 537 MB of swf, fully coalesced.
// ---------------------------------------------------------------------------
__global__ void k4_pool(const float* __restrict__ swf,
                        const float* __restrict__ weight,
                        float* __restrict__ partial) {
    const int b = blockIdx.y, c = blockIdx.x;
    __shared__ float sw[NPER];
    for (int i = threadIdx.x; i < NPER; i += blockDim.x)
        sw[i] = weight[(size_t)b * N_ + c * NPER + i];
    __syncthreads();

    const float4* x = (const float4*)(swf + ((size_t)b * N_ + (size_t)c * NPER) * DW_);
    const int t = threadIdx.x;
    float4 acc = make_float4(0.f, 0.f, 0.f, 0.f);
    #pragma unroll 4
    for (int n = 0; n < NPER; n++) {
        float wn = sw[n];
        float4 v = x[(size_t)n * (DW_ / 4) + t];
        acc.x += wn * v.x; acc.y += wn * v.y;
        acc.z += wn * v.z; acc.w += wn * v.w;
    }
    ((float4*)partial)[((size_t)b * NCHUNK + c) * (DW_ / 4) + t] = acc;
}

// ---------------------------------------------------------------------------
// K5: out[b] = concat(senti_feats[b], sum_c partial[b,c,:])
// grid = B_, block = 256.
// ---------------------------------------------------------------------------
__global__ void k5_finish(const float* __restrict__ senti,
                          const float* __restrict__ partial,
                          float* __restrict__ out) {
    const int b = blockIdx.x, t = threadIdx.x;
    float4* orow = (float4*)(out + (size_t)b * (DS_ + DW_));
    // copy senti_feats (256 float4)
    orow[t] = ((const float4*)(senti + (size_t)b * DS_))[t];
    // reduce partials (deterministic fixed order)
    float4 acc = make_float4(0.f, 0.f, 0.f, 0.f);
    #pragma unroll
    for (int c = 0; c < NCHUNK; c++) {
        float4 v = ((const float4*)partial)[((size_t)b * NCHUNK + c) * (DW_ / 4) + t];
        acc.x += v.x; acc.y += v.y; acc.z += v.z; acc.w += v.w;
    }
    orow[DS_ / 4 + t] = acc;
}

// ---------------------------------------------------------------------------
extern "C" void kernel_launch(void* const* d_in, const int* in_sizes, int n_in,
                              void* d_out, int out_size) {
    const float* h      = (const float*)d_in[0];  // [B, RNN]
    const float* senti  = (const float*)d_in[1];  // [B, DS]
    const float* swf    = (const float*)d_in[2];  // [B, N, DW]
    const float* p      = (const float*)d_in[3];  // [B, N, A]
    const float* W      = (const float*)d_in[4];  // [A, RNN]
    const float* bvec   = (const float*)d_in[5];  // [A]
    const float* walpha = (const float*)d_in[6];  // [A]
    // d_in[7] = b_alpha: softmax-invariant, ignored.

    float* hw;      cudaGetSymbolAddress((void**)&hw,      g_hword);
    float* scores;  cudaGetSymbolAddress((void**)&scores,  g_scores);
    float* partial; cudaGetSymbolAddress((void**)&partial, g_partial);

    k1_hword<<<A_, 128>>>(h, W, bvec, hw);
    k2_scores<<<dim3(N_ / 8, B_), 256>>>(p, hw, walpha, scores);
    k3_softmax<<<B_, 256>>>(scores);
    k4_pool<<<dim3(NCHUNK, B_), 256>>>(swf, scores, partial);
    k5_finish<<<B_, 256>>>(senti, partial, (float*)d_out);
}

// round 3
// speedup vs baseline: 1.2130x; 1.2130x over previous
#include <cuda_runtime.h>
#include <cstdint>

// Shapes (fixed for this problem)
#define B_   64
#define N_   2048
#define A_   512
#define RNN_ 1024
#define DW_  1024
#define DS_  1024
#define NCHUNK 16
#define NPER   (N_ / NCHUNK)   // 128

// k1 split-K GEMM config
#define KSPLIT 16
#define KCH    (RNN_ / KSPLIT)   // 64

// Scratch (device globals: no allocation allowed)
__device__ float g_pk1[KSPLIT * B_ * A_];       // 2 MB   (k1 partials)
__device__ float g_hword[B_ * A_];              // 128 KB
__device__ float g_scores[B_ * N_];             // 512 KB (reused as softmax weights)
__device__ float g_partial[B_ * NCHUNK * DW_];  // 4 MB

__device__ __forceinline__ float tanh_fast(float x) {
    float r;
    asm("tanh.approx.f32 %0, %1;" : "=f"(r) : "f"(x));
    return r;
}

__device__ __forceinline__ float warp_sum(float v) {
    #pragma unroll
    for (int o = 16; o; o >>= 1) v += __shfl_xor_sync(0xffffffffu, v, o);
    return v;
}

// ---------------------------------------------------------------------------
// K1: split-K tiled GEMM. pk1[ks][b][a] = sum_{k in chunk ks} h[b,k] * W[a,k]
// grid = (A_/32 = 16, KSPLIT = 16), block = 256.
// smem tiles: sH[64][KCH], sW[32][KCH] (padded). Each thread owns (b, 8 a's).
// Per-CTA traffic ~24 KB -> total ~6 MB (vs 134 MB in the old k1).
// ---------------------------------------------------------------------------
__global__ void k1_gemm(const float* __restrict__ h,
                        const float* __restrict__ W,
                        float* __restrict__ pk1) {
    const int a0 = blockIdx.x * 32;
    const int k0 = blockIdx.y * KCH;

    __shared__ float sH[64][KCH + 4];   // stride 68 floats: conflict-free LDS.128
    __shared__ float sW[32][KCH + 4];

    // Stage h tile: 64 rows x 16 float4
    for (int idx = threadIdx.x; idx < 64 * (KCH / 4); idx += 256) {
        const int row = idx >> 4, kk = idx & 15;
        float4 v = *(const float4*)(h + (size_t)row * RNN_ + k0 + kk * 4);
        *(float4*)(&sH[row][kk * 4]) = v;
    }
    // Stage W tile: 32 rows x 16 float4
    for (int idx = threadIdx.x; idx < 32 * (KCH / 4); idx += 256) {
        const int row = idx >> 4, kk = idx & 15;
        float4 v = *(const float4*)(W + (size_t)(a0 + row) * RNN_ + k0 + kk * 4);
        *(float4*)(&sW[row][kk * 4]) = v;
    }
    __syncthreads();

    const int b  = threadIdx.x & 63;
    const int ag = threadIdx.x >> 6;        // 0..3, owns a's [a0+ag*8, a0+ag*8+8)

    float acc[8] = {0.f, 0.f, 0.f, 0.f, 0.f, 0.f, 0.f, 0.f};
    #pragma unroll 8
    for (int k4 = 0; k4 < KCH / 4; k4++) {
        const float4 hv = *(const float4*)(&sH[b][k4 * 4]);
        #pragma unroll
        for (int j = 0; j < 8; j++) {
            const float4 wv = *(const float4*)(&sW[ag * 8 + j][k4 * 4]);
            acc[j] += hv.x * wv.x + hv.y * wv.y + hv.z * wv.z + hv.w * wv.w;
        }
    }

    float* dst = pk1 + ((size_t)blockIdx.y * B_ + b) * A_ + a0 + ag * 8;
    #pragma unroll
    for (int j = 0; j < 8; j++) dst[j] = acc[j];
}

// ---------------------------------------------------------------------------
// K1r: hw[b][a] = bias[a] + sum_ks pk1[ks][b][a].  float4-wide, grid 32 x 256.
// ---------------------------------------------------------------------------
__global__ void k1_reduce(const float* __restrict__ pk1,
                          const float* __restrict__ bias,
                          float* __restrict__ hw) {
    const int idx = blockIdx.x * 256 + threadIdx.x;   // f4 index in [64][128]
    const int c = idx & 127;                          // f4 col within row
    float4 acc = ((const float4*)bias)[c];
    const int b = idx >> 7;
    #pragma unroll
    for (int ks = 0; ks < KSPLIT; ks++) {
        float4 v = ((const float4*)pk1)[((size_t)ks * B_ + b) * (A_ / 4) + c];
        acc.x += v.x; acc.y += v.y; acc.z += v.z; acc.w += v.w;
    }
    ((float4*)hw)[idx] = acc;
}

// ---------------------------------------------------------------------------
// K2: scores[b,n] = sum_a tanh(p[b,n,a] + hw[b,a]) * walpha[a]
// grid = (N_/32, B_), block = 256 (8 warps, 4 n per warp).
// hw row + walpha register-cached per lane (no smem restaging), __ldcs on p.
// ---------------------------------------------------------------------------
__global__ void k2_scores(const float* __restrict__ p,
                          const float* __restrict__ hw,
                          const float* __restrict__ walpha,
                          float* __restrict__ scores) {
    const int b = blockIdx.y;
    const int warp = threadIdx.x >> 5, lane = threadIdx.x & 31;
    const int n0 = blockIdx.x * 32 + warp * 4;

    float4 hv[4], wv[4];
    #pragma unroll
    for (int i = 0; i < 4; i++) {
        hv[i] = __ldg((const float4*)(hw + (size_t)b * A_) + lane + 32 * i);
        wv[i] = __ldg((const float4*)walpha + lane + 32 * i);
    }

    #pragma unroll
    for (int nn = 0; nn < 4; nn++) {
        const float4* pr = (const float4*)(p + ((size_t)b * N_ + n0 + nn) * A_);
        float4 v0 = __ldcs(pr + lane);
        float4 v1 = __ldcs(pr + lane + 32);
        float4 v2 = __ldcs(pr + lane + 64);
        float4 v3 = __ldcs(pr + lane + 96);

        float acc;
        acc  = tanh_fast(v0.x + hv[0].x) * wv[0].x;
        acc += tanh_fast(v0.y + hv[0].y) * wv[0].y;
        acc += tanh_fast(v0.z + hv[0].z) * wv[0].z;
        acc += tanh_fast(v0.w + hv[0].w) * wv[0].w;
        acc += tanh_fast(v1.x + hv[1].x) * wv[1].x;
        acc += tanh_fast(v1.y + hv[1].y) * wv[1].y;
        acc += tanh_fast(v1.z + hv[1].z) * wv[1].z;
        acc += tanh_fast(v1.w + hv[1].w) * wv[1].w;
        acc += tanh_fast(v2.x + hv[2].x) * wv[2].x;
        acc += tanh_fast(v2.y + hv[2].y) * wv[2].y;
        acc += tanh_fast(v2.z + hv[2].z) * wv[2].z;
        acc += tanh_fast(v2.w + hv[2].w) * wv[2].w;
        acc += tanh_fast(v3.x + hv[3].x) * wv[3].x;
        acc += tanh_fast(v3.y + hv[3].y) * wv[3].y;
        acc += tanh_fast(v3.z + hv[3].z) * wv[3].z;
        acc += tanh_fast(v3.w + hv[3].w) * wv[3].w;

        acc = warp_sum(acc);
        if (lane == 0) scores[(size_t)b * N_ + n0 + nn] = acc;
    }
}

// ---------------------------------------------------------------------------
// K3: in-place softmax over N per row. grid = B_, block = 256.
// ---------------------------------------------------------------------------
__global__ void k3_softmax(float* __restrict__ scores) {
    const int b = blockIdx.x;
    __shared__ float s[N_];
    __shared__ float red[32];
    float* row = scores + (size_t)b * N_;

    for (int i = threadIdx.x; i < N_ / 4; i += blockDim.x)
        ((float4*)s)[i] = ((float4*)row)[i];
    __syncthreads();

    const int warp = threadIdx.x >> 5, lane = threadIdx.x & 31;

    float m = -3.4e38f;
    for (int i = threadIdx.x; i < N_; i += blockDim.x) m = fmaxf(m, s[i]);
    #pragma unroll
    for (int o = 16; o; o >>= 1) m = fmaxf(m, __shfl_xor_sync(0xffffffffu, m, o));
    if (lane == 0) red[warp] = m;
    __syncthreads();
    m = red[lane & 7];
    #pragma unroll
    for (int o = 4; o; o >>= 1) m = fmaxf(m, __shfl_xor_sync(0xffffffffu, m, o));
    m = __shfl_sync(0xffffffffu, m, 0);

    float sum = 0.f;
    for (int i = threadIdx.x; i < N_; i += blockDim.x) {
        float e = __expf(s[i] - m);
        s[i] = e;
        sum += e;
    }
    sum = warp_sum(sum);
    if (lane == 0) red[warp] = sum;
    __syncthreads();
    sum = red[lane & 7];
    #pragma unroll
    for (int o = 4; o; o >>= 1) sum += __shfl_xor_sync(0xffffffffu, sum, o);
    sum = __shfl_sync(0xffffffffu, sum, 0);
    const float inv = 1.0f / sum;
    __syncthreads();

    for (int i = threadIdx.x; i < N_; i += blockDim.x)
        row[i] = s[i] * inv;
}

// ---------------------------------------------------------------------------
// K4: partial[b,c,d] = sum_{n in chunk c} weight[b,n] * swf[b,n,d]
// grid = (NCHUNK, B_), block = 256. __ldcs streaming loads, unroll 8.
// ---------------------------------------------------------------------------
__global__ void k4_pool(const float* __restrict__ swf,
                        const float* __restrict__ weight,
                        float* __restrict__ partial) {
    const int b = blockIdx.y, c = blockIdx.x;
    __shared__ float sw[NPER];
    for (int i = threadIdx.x; i < NPER; i += blockDim.x)
        sw[i] = weight[(size_t)b * N_ + c * NPER + i];
    __syncthreads();

    const float4* x = (const float4*)(swf + ((size_t)b * N_ + (size_t)c * NPER) * DW_);
    const int t = threadIdx.x;
    float4 acc = make_float4(0.f, 0.f, 0.f, 0.f);
    #pragma unroll 8
    for (int n = 0; n < NPER; n++) {
        const float wn = sw[n];
        const float4 v = __ldcs(x + (size_t)n * (DW_ / 4) + t);
        acc.x += wn * v.x; acc.y += wn * v.y;
        acc.z += wn * v.z; acc.w += wn * v.w;
    }
    ((float4*)partial)[((size_t)b * NCHUNK + c) * (DW_ / 4) + t] = acc;
}

// ---------------------------------------------------------------------------
// K5: out[b] = concat(senti_feats[b], sum_c partial[b,c,:]). grid = B_, 256.
// ---------------------------------------------------------------------------
__global__ void k5_finish(const float* __restrict__ senti,
                          const float* __restrict__ partial,
                          float* __restrict__ out) {
    const int b = blockIdx.x, t = threadIdx.x;
    float4* orow = (float4*)(out + (size_t)b * (DS_ + DW_));
    orow[t] = ((const float4*)(senti + (size_t)b * DS_))[t];
    float4 acc = make_float4(0.f, 0.f, 0.f, 0.f);
    #pragma unroll
    for (int c = 0; c < NCHUNK; c++) {
        float4 v = __ldg(((const float4*)partial) + ((size_t)b * NCHUNK + c) * (DW_ / 4) + t);
        acc.x += v.x; acc.y += v.y; acc.z += v.z; acc.w += v.w;
    }
    orow[DS_ / 4 + t] = acc;
}

// ---------------------------------------------------------------------------
extern "C" void kernel_launch(void* const* d_in, const int* in_sizes, int n_in,
                              void* d_out, int out_size) {
    const float* h      = (const float*)d_in[0];  // [B, RNN]
    const float* senti  = (const float*)d_in[1];  // [B, DS]
    const float* swf    = (const float*)d_in[2];  // [B, N, DW]
    const float* p      = (const float*)d_in[3];  // [B, N, A]
    const float* W      = (const float*)d_in[4];  // [A, RNN]
    const float* bvec   = (const float*)d_in[5];  // [A]
    const float* walpha = (const float*)d_in[6];  // [A]
    // d_in[7] = b_alpha: softmax-invariant, ignored.

    float* pk1;     cudaGetSymbolAddress((void**)&pk1,     g_pk1);
    float* hw;      cudaGetSymbolAddress((void**)&hw,      g_hword);
    float* scores;  cudaGetSymbolAddress((void**)&scores,  g_scores);
    float* partial; cudaGetSymbolAddress((void**)&partial, g_partial);

    k1_gemm  <<<dim3(A_ / 32, KSPLIT), 256>>>(h, W, pk1);
    k1_reduce<<<(B_ * A_ / 4) / 256, 256>>>(pk1, bvec, hw);
    k2_scores<<<dim3(N_ / 32, B_), 256>>>(p, hw, walpha, scores);
    k3_softmax<<<B_, 256>>>(scores);
    k4_pool  <<<dim3(NCHUNK, B_), 256>>>(swf, scores, partial);
    k5_finish<<<B_, 256>>>(senti, partial, (float*)d_out);
}